// round 1
// baseline (speedup 1.0000x reference)
#include <cuda_runtime.h>

// DiffOmegaVectorNorm: masked vorticity-difference L2 norm, reduced to a scalar.
//
// Key identities used:
//   omega(P)-omega(T) = omega(P-T)                  (linearity)
//   scale/(2*delta) = 10/10 = 1                     (coefficient-free stencil)
//   active(voxel) = all 27 mask neighbors == 1      (b*(1-nw) gate)
//   num_grids = #active interior voxels
//
// Shapes: P,T (2,4,64,256,256) f32; M (2,1,64,256,256) f32. Output: 1 f32.

#define TZ 4
#define TY 8

__device__ double g_sum;
__device__ unsigned long long g_cnt;

__global__ void dovn_init_kernel() {
    g_sum = 0.0;
    g_cnt = 0ull;
}

__global__ void dovn_final_kernel(float* out) {
    out[0] = (float)(g_sum / (double)g_cnt);
}

__global__ __launch_bounds__(256) void dovn_main_kernel(
    const float* __restrict__ P,
    const float* __restrict__ T,
    const float* __restrict__ M)
{
    __shared__ unsigned int rb[TZ + 2][TY + 2][8];   // raw mask bits per row (256 bits = 8 words)
    __shared__ unsigned int axm[TZ + 2][TY + 2][8];  // x-direction 3-min bits
    __shared__ unsigned int act[TZ][TY][8];          // final active bits (27-AND + bounds)
    __shared__ float wsum[8];
    __shared__ int   wcnt[8];

    const int x    = threadIdx.x;        // x coordinate, 0..255
    const int warp = x >> 5;
    const int lane = x & 31;
    const int y0   = 1 + blockIdx.x * TY;  // first interior y of tile
    const int z0   = 1 + blockIdx.y * TZ;  // first interior z of tile
    const int b    = blockIdx.z;

    const unsigned mbase = (unsigned)b * 64u * 65536u;  // mask: (b, z, y, x)

    // ---- 1. Load mask halo rows, pack to bitmasks via ballot ----
    #pragma unroll
    for (int zz = 0; zz < TZ + 2; ++zz) {
        const int gz = z0 - 1 + zz;
        #pragma unroll
        for (int yy = 0; yy < TY + 2; ++yy) {
            const int gy = y0 - 1 + yy;
            float m = 0.0f;
            if (gz <= 63 && gy <= 255)
                m = M[mbase + (unsigned)gz * 65536u + (unsigned)gy * 256u + (unsigned)x];
            unsigned bal = __ballot_sync(0xFFFFFFFFu, m > 0.5f);
            if (lane == 0) rb[zz][yy][warp] = bal;
        }
    }
    __syncthreads();

    // ---- 2. x-direction 3-wide AND (min over x-1,x,x+1) ----
    for (int idx = x; idx < (TZ + 2) * (TY + 2) * 8; idx += 256) {
        const int zz = idx / ((TY + 2) * 8);
        const int r  = idx % ((TY + 2) * 8);
        const int yy = r >> 3;
        const int j  = r & 7;
        const unsigned bm = rb[zz][yy][j];
        const unsigned bl = (j > 0) ? rb[zz][yy][j - 1] : 0u;
        const unsigned bh = (j < 7) ? rb[zz][yy][j + 1] : 0u;
        axm[zz][yy][j] = bm & ((bm << 1) | (bl >> 31)) & ((bm >> 1) | (bh << 31));
    }
    __syncthreads();

    // ---- 3. 3x3 AND in (z,y) + bounds -> active bits (exactly 256 words) ----
    {
        const int zz = x >> 6;         // 0..3
        const int yy = (x >> 3) & 7;   // 0..7
        const int j  = x & 7;          // 0..7
        const int hz = zz + 1, hy = yy + 1;
        unsigned a = 0xFFFFFFFFu;
        #pragma unroll
        for (int dz = -1; dz <= 1; ++dz)
            #pragma unroll
            for (int dy = -1; dy <= 1; ++dy)
                a &= axm[hz + dz][hy + dy][j];
        if (j == 0) a &= 0xFFFFFFFEu;   // x >= 1
        if (j == 7) a &= 0x7FFFFFFFu;   // x <= 254
        if (z0 + zz > 62)  a = 0u;      // interior z bound
        if (y0 + yy > 254) a = 0u;      // interior y bound
        act[zz][yy][j] = a;
    }
    __syncthreads();

    // ---- 4. Gated vorticity-diff stencil over active voxels ----
    float lsum = 0.0f;
    int   lcnt = 0;
    const int      wj  = x >> 5;
    const unsigned bit = 1u << (x & 31);
    const unsigned cb  = (unsigned)b * 4u * 64u * 65536u;
    const unsigned CS  = 64u * 65536u;   // channel stride
    const unsigned SZ  = 65536u;         // z stride
    const unsigned SY  = 256u;           // y stride

    #pragma unroll
    for (int zz = 0; zz < TZ; ++zz) {
        #pragma unroll
        for (int yy = 0; yy < TY; ++yy) {
            if (act[zz][yy][wj] & bit) {
                const unsigned gz = (unsigned)(z0 + zz);
                const unsigned gy = (unsigned)(y0 + yy);
                const unsigned o1 = cb + 1u * CS + gz * SZ + gy * SY + (unsigned)x; // u
                const unsigned o2 = o1 + CS;                                        // v
                const unsigned o3 = o2 + CS;                                        // w

                const float u_zp = P[o1 + SZ] - T[o1 + SZ];
                const float u_zm = P[o1 - SZ] - T[o1 - SZ];
                const float u_yp = P[o1 + SY] - T[o1 + SY];
                const float u_ym = P[o1 - SY] - T[o1 - SY];
                const float v_zp = P[o2 + SZ] - T[o2 + SZ];
                const float v_zm = P[o2 - SZ] - T[o2 - SZ];
                const float v_xp = P[o2 + 1u] - T[o2 + 1u];
                const float v_xm = P[o2 - 1u] - T[o2 - 1u];
                const float w_yp = P[o3 + SY] - T[o3 + SY];
                const float w_ym = P[o3 - SY] - T[o3 - SY];
                const float w_xp = P[o3 + 1u] - T[o3 + 1u];
                const float w_xm = P[o3 - 1u] - T[o3 - 1u];

                const float vx = (w_yp - w_ym) - (v_zp - v_zm);
                const float vy = (u_zp - u_zm) - (w_xp - w_xm);
                const float vz = (v_xp - v_xm) - (u_yp - u_ym);

                lsum += sqrtf(vx * vx + vy * vy + vz * vz);
                lcnt++;
            }
        }
    }

    // ---- 5. Block reduction + global atomics ----
    #pragma unroll
    for (int off = 16; off; off >>= 1) {
        lsum += __shfl_down_sync(0xFFFFFFFFu, lsum, off);
        lcnt += __shfl_down_sync(0xFFFFFFFFu, lcnt, off);
    }
    if (lane == 0) { wsum[warp] = lsum; wcnt[warp] = lcnt; }
    __syncthreads();
    if (x == 0) {
        float s = 0.0f;
        int   c = 0;
        #pragma unroll
        for (int i = 0; i < 8; ++i) { s += wsum[i]; c += wcnt[i]; }
        if (c > 0) {
            atomicAdd(&g_sum, (double)s);
            atomicAdd(&g_cnt, (unsigned long long)c);
        }
    }
}

extern "C" void kernel_launch(void* const* d_in, const int* in_sizes, int n_in,
                              void* d_out, int out_size) {
    const float* P = (const float*)d_in[0];
    const float* T = (const float*)d_in[1];
    const float* M = (const float*)d_in[2];

    dovn_init_kernel<<<1, 1>>>();
    dim3 grid(32 /*y tiles: 254/8*/, 16 /*z tiles: 62/4*/, 2 /*batch*/);
    dovn_main_kernel<<<grid, 256>>>(P, T, M);
    dovn_final_kernel<<<1, 1>>>((float*)d_out);
}